// round 1
// baseline (speedup 1.0000x reference)
#include <cuda_runtime.h>
#include <math.h>

#define EPS 1e-5f

constexpr int BATCH = 32;
constexpr int S = 1024;
constexpr int D = 1024;

constexpr int BM = 128;
constexpr int BN = 128;
constexpr int BK = 16;
constexpr int TM = 8;
constexpr int TN = 8;
constexpr int NTHREADS = 256;

// Scratch (allocation-free requirement -> __device__ globals)
__device__ float g_xtran[(size_t)BATCH * S * D];     // 128 MB
__device__ float g_weights[(size_t)BATCH * S * S];   // 128 MB
__device__ float g_rowsum[BATCH * S];

// ---------------------------------------------------------------------------
// GEMM1 (NT): xtran[m,n] = sum_k X[m,k] * W[n,k] + bias[n]
//   X: [32768, 1024] row-major, W: [1024, 1024] row-major (both K-major)
// ---------------------------------------------------------------------------
__global__ __launch_bounds__(NTHREADS)
void gemm1_kernel(const float* __restrict__ X,
                  const float* __restrict__ W,
                  const float* __restrict__ bias)
{
    const int K = D;
    const int N = D;

    __shared__ float As[BK][BM];
    __shared__ float Bs[BK][BN];

    const int tid = threadIdx.x;
    const int bm = blockIdx.y * BM;
    const int bn = blockIdx.x * BN;
    const int tx = tid % 16;
    const int ty = tid / 16;

    float acc[TM][TN];
#pragma unroll
    for (int i = 0; i < TM; i++)
#pragma unroll
        for (int j = 0; j < TN; j++) acc[i][j] = 0.f;

    for (int k0 = 0; k0 < K; k0 += BK) {
#pragma unroll
        for (int l = 0; l < 2; l++) {
            int idx = tid + l * NTHREADS;
            int row = idx >> 2;
            int c4  = (idx & 3) * 4;
            float4 v = *(const float4*)&X[(size_t)(bm + row) * K + k0 + c4];
            As[c4 + 0][row] = v.x; As[c4 + 1][row] = v.y;
            As[c4 + 2][row] = v.z; As[c4 + 3][row] = v.w;
        }
#pragma unroll
        for (int l = 0; l < 2; l++) {
            int idx = tid + l * NTHREADS;
            int row = idx >> 2;
            int c4  = (idx & 3) * 4;
            float4 v = *(const float4*)&W[(size_t)(bn + row) * K + k0 + c4];
            Bs[c4 + 0][row] = v.x; Bs[c4 + 1][row] = v.y;
            Bs[c4 + 2][row] = v.z; Bs[c4 + 3][row] = v.w;
        }
        __syncthreads();

#pragma unroll
        for (int kk = 0; kk < BK; kk++) {
            float a[TM], b[TN];
            *(float4*)&a[0] = *(const float4*)&As[kk][ty * TM];
            *(float4*)&a[4] = *(const float4*)&As[kk][ty * TM + 4];
            *(float4*)&b[0] = *(const float4*)&Bs[kk][tx * TN];
            *(float4*)&b[4] = *(const float4*)&Bs[kk][tx * TN + 4];
#pragma unroll
            for (int i = 0; i < TM; i++)
#pragma unroll
                for (int j = 0; j < TN; j++) acc[i][j] += a[i] * b[j];
        }
        __syncthreads();
    }

#pragma unroll
    for (int i = 0; i < TM; i++) {
        int m = bm + ty * TM + i;
        int n = bn + tx * TN;
        float4 r0, r1;
        r0.x = acc[i][0] + bias[n + 0]; r0.y = acc[i][1] + bias[n + 1];
        r0.z = acc[i][2] + bias[n + 2]; r0.w = acc[i][3] + bias[n + 3];
        r1.x = acc[i][4] + bias[n + 4]; r1.y = acc[i][5] + bias[n + 5];
        r1.z = acc[i][6] + bias[n + 6]; r1.w = acc[i][7] + bias[n + 7];
        *(float4*)&g_xtran[(size_t)m * N + n]     = r0;
        *(float4*)&g_xtran[(size_t)m * N + n + 4] = r1;
    }
}

// ---------------------------------------------------------------------------
// GEMM2 (NT, per batch): w[s,t] = sum_d xtran[b,s,d] * x[b,t,d]
// Epilogue: * 1/(|s-t|+eps) * opinion[b,s] -> exp(tanh) -> diag mask
// ---------------------------------------------------------------------------
__global__ __launch_bounds__(NTHREADS)
void gemm2_kernel(const float* __restrict__ X,
                  const float* __restrict__ go,
                  const float* __restrict__ po,
                  const float* __restrict__ gprob)
{
    const int K = D;
    const int b = blockIdx.z;
    const float* A = g_xtran + (size_t)b * S * D;
    const float* B = X       + (size_t)b * S * D;
    float*       C = g_weights + (size_t)b * S * S;

    __shared__ float As[BK][BM];
    __shared__ float Bs[BK][BN];

    const int tid = threadIdx.x;
    const int bm = blockIdx.y * BM;
    const int bn = blockIdx.x * BN;
    const int tx = tid % 16;
    const int ty = tid / 16;

    float acc[TM][TN];
#pragma unroll
    for (int i = 0; i < TM; i++)
#pragma unroll
        for (int j = 0; j < TN; j++) acc[i][j] = 0.f;

    for (int k0 = 0; k0 < K; k0 += BK) {
#pragma unroll
        for (int l = 0; l < 2; l++) {
            int idx = tid + l * NTHREADS;
            int row = idx >> 2;
            int c4  = (idx & 3) * 4;
            float4 v = *(const float4*)&A[(size_t)(bm + row) * K + k0 + c4];
            As[c4 + 0][row] = v.x; As[c4 + 1][row] = v.y;
            As[c4 + 2][row] = v.z; As[c4 + 3][row] = v.w;
        }
#pragma unroll
        for (int l = 0; l < 2; l++) {
            int idx = tid + l * NTHREADS;
            int row = idx >> 2;
            int c4  = (idx & 3) * 4;
            float4 v = *(const float4*)&B[(size_t)(bn + row) * K + k0 + c4];
            Bs[c4 + 0][row] = v.x; Bs[c4 + 1][row] = v.y;
            Bs[c4 + 2][row] = v.z; Bs[c4 + 3][row] = v.w;
        }
        __syncthreads();

#pragma unroll
        for (int kk = 0; kk < BK; kk++) {
            float a[TM], bf[TN];
            *(float4*)&a[0]  = *(const float4*)&As[kk][ty * TM];
            *(float4*)&a[4]  = *(const float4*)&As[kk][ty * TM + 4];
            *(float4*)&bf[0] = *(const float4*)&Bs[kk][tx * TN];
            *(float4*)&bf[4] = *(const float4*)&Bs[kk][tx * TN + 4];
#pragma unroll
            for (int i = 0; i < TM; i++)
#pragma unroll
                for (int j = 0; j < TN; j++) acc[i][j] += a[i] * bf[j];
        }
        __syncthreads();
    }

    const float gp = *gprob;

#pragma unroll
    for (int i = 0; i < TM; i++) {
        int s = bm + ty * TM + i;
        const float* goP = go + ((size_t)b * S + s) * 5;
        const float* poP = po + ((size_t)b * S + s) * 5;
        float ow = gp * (goP[1] + goP[2]) + (1.f - gp) * (poP[3] + poP[4]);

        float4 r0, r1;
        float* rr = (float*)&r0;  // rr[0..3] then r1
#pragma unroll
        for (int j = 0; j < TN; j++) {
            int t = bn + tx * TN + j;
            float loc = fabsf((float)(s - t));
            float wv = acc[i][j] * ow / (loc + EPS);
            wv = expf(tanhf(wv));
            if (s == t) wv = 0.f;
            if (j < 4) ((float*)&r0)[j] = wv;
            else       ((float*)&r1)[j - 4] = wv;
        }
        (void)rr;
        int t0 = bn + tx * TN;
        *(float4*)&C[(size_t)s * S + t0]     = r0;
        *(float4*)&C[(size_t)s * S + t0 + 4] = r1;
    }
}

// ---------------------------------------------------------------------------
// Rowsum over weights rows [B*S rows, S cols]
// ---------------------------------------------------------------------------
__global__ __launch_bounds__(NTHREADS)
void rowsum_kernel()
{
    const int row = blockIdx.x;
    const float* p = g_weights + (size_t)row * S;
    const int tid = threadIdx.x;

    // 256 threads * float4 = 1024 elements exactly
    float4 v = *(const float4*)&p[tid * 4];
    float s = v.x + v.y + v.z + v.w;

#pragma unroll
    for (int off = 16; off > 0; off >>= 1)
        s += __shfl_down_sync(0xFFFFFFFFu, s, off);

    __shared__ float warpsum[8];
    if ((tid & 31) == 0) warpsum[tid >> 5] = s;
    __syncthreads();
    if (tid < 8) {
        float t = warpsum[tid];
#pragma unroll
        for (int off = 4; off > 0; off >>= 1)
            t += __shfl_down_sync(0xFFu, t, off);
        if (tid == 0) g_rowsum[row] = t;
    }
}

// ---------------------------------------------------------------------------
// GEMM3 (NN, per batch): out[s,d] = (1/(rowsum+eps)) * sum_t w[s,t] * x[b,t,d]
// ---------------------------------------------------------------------------
__global__ __launch_bounds__(NTHREADS)
void gemm3_kernel(const float* __restrict__ X, float* __restrict__ out)
{
    const int K = S;   // contraction over t
    const int N = D;
    const int b = blockIdx.z;
    const float* A = g_weights + (size_t)b * S * S;
    const float* B = X         + (size_t)b * S * D;
    float*       C = out       + (size_t)b * S * D;

    __shared__ float As[BK][BM];
    __shared__ float Bs[BK][BN];

    const int tid = threadIdx.x;
    const int bm = blockIdx.y * BM;
    const int bn = blockIdx.x * BN;
    const int tx = tid % 16;
    const int ty = tid / 16;

    float acc[TM][TN];
#pragma unroll
    for (int i = 0; i < TM; i++)
#pragma unroll
        for (int j = 0; j < TN; j++) acc[i][j] = 0.f;

    for (int k0 = 0; k0 < K; k0 += BK) {
        // A tile: rows of weights (K-major)
#pragma unroll
        for (int l = 0; l < 2; l++) {
            int idx = tid + l * NTHREADS;
            int row = idx >> 2;
            int c4  = (idx & 3) * 4;
            float4 v = *(const float4*)&A[(size_t)(bm + row) * K + k0 + c4];
            As[c4 + 0][row] = v.x; As[c4 + 1][row] = v.y;
            As[c4 + 2][row] = v.z; As[c4 + 3][row] = v.w;
        }
        // B tile: [K, N] row-major -> direct
#pragma unroll
        for (int l = 0; l < 2; l++) {
            int idx = tid + l * NTHREADS;
            int kr = idx >> 5;          // 0..15
            int c4 = (idx & 31) * 4;    // 0..124
            float4 v = *(const float4*)&B[(size_t)(k0 + kr) * N + bn + c4];
            *(float4*)&Bs[kr][c4] = v;
        }
        __syncthreads();

#pragma unroll
        for (int kk = 0; kk < BK; kk++) {
            float a[TM], bf[TN];
            *(float4*)&a[0]  = *(const float4*)&As[kk][ty * TM];
            *(float4*)&a[4]  = *(const float4*)&As[kk][ty * TM + 4];
            *(float4*)&bf[0] = *(const float4*)&Bs[kk][tx * TN];
            *(float4*)&bf[4] = *(const float4*)&Bs[kk][tx * TN + 4];
#pragma unroll
            for (int i = 0; i < TM; i++)
#pragma unroll
                for (int j = 0; j < TN; j++) acc[i][j] += a[i] * bf[j];
        }
        __syncthreads();
    }

#pragma unroll
    for (int i = 0; i < TM; i++) {
        int s = bm + ty * TM + i;
        float sc = 1.f / (g_rowsum[b * S + s] + EPS);
        int n = bn + tx * TN;
        float4 r0, r1;
        r0.x = acc[i][0] * sc; r0.y = acc[i][1] * sc;
        r0.z = acc[i][2] * sc; r0.w = acc[i][3] * sc;
        r1.x = acc[i][4] * sc; r1.y = acc[i][5] * sc;
        r1.z = acc[i][6] * sc; r1.w = acc[i][7] * sc;
        *(float4*)&C[(size_t)s * N + n]     = r0;
        *(float4*)&C[(size_t)s * N + n + 4] = r1;
    }
}

// ---------------------------------------------------------------------------
extern "C" void kernel_launch(void* const* d_in, const int* in_sizes, int n_in,
                              void* d_out, int out_size)
{
    const float* x     = (const float*)d_in[0];  // [32,1024,1024]
    const float* W     = (const float*)d_in[1];  // [1024,1024]
    const float* bias  = (const float*)d_in[2];  // [1024]
    const float* go    = (const float*)d_in[3];  // [32,1024,5]
    const float* po    = (const float*)d_in[4];  // [32,1024,5]
    const float* gprob = (const float*)d_in[5];  // scalar
    float* out = (float*)d_out;

    dim3 threads(NTHREADS);

    // GEMM1: [32768,1024] x [1024,1024]^T
    gemm1_kernel<<<dim3(D / BN, (BATCH * S) / BM), threads>>>(x, W, bias);

    // GEMM2: per-batch [1024,1024] x [1024,1024]^T + epilogue
    gemm2_kernel<<<dim3(S / BN, S / BM, BATCH), threads>>>(x, go, po, gprob);

    // Rowsum over 32768 rows
    rowsum_kernel<<<dim3(BATCH * S), threads>>>();

    // GEMM3: per-batch [1024,1024] x [1024,1024] + normalize epilogue
    gemm3_kernel<<<dim3(D / BN, S / BM, BATCH), threads>>>(x, out);
}

// round 3
// speedup vs baseline: 1.7544x; 1.7544x over previous
#include <cuda_runtime.h>
#include <cuda_bf16.h>
#include <cstdint>
#include <math.h>

#define EPS 1e-5f

constexpr int BATCH = 32;
constexpr int S = 1024;
constexpr int D = 1024;

// Scratch (allocation-free requirement -> __device__ globals)
__device__ float g_xtran[(size_t)BATCH * S * D];     // 128 MB
__device__ float g_weights[(size_t)BATCH * S * S];   // 128 MB
__device__ float g_xT[(size_t)BATCH * S * D];        // 128 MB
__device__ float g_rowsum[BATCH * S];

// ---------------------------------------------------------------------------
// helpers
// ---------------------------------------------------------------------------
__device__ __forceinline__ uint32_t smem_u32(const void* p) {
    uint32_t a;
    asm("{ .reg .u64 t; cvta.to.shared.u64 t, %1; cvt.u32.u64 %0, t; }" : "=r"(a) : "l"(p));
    return a;
}

__device__ __forceinline__ void ldsm4(uint32_t& r0, uint32_t& r1, uint32_t& r2, uint32_t& r3,
                                      uint32_t addr) {
    asm volatile("ldmatrix.sync.aligned.m8n8.x4.shared.b16 {%0,%1,%2,%3}, [%4];"
                 : "=r"(r0), "=r"(r1), "=r"(r2), "=r"(r3) : "r"(addr));
}

__device__ __forceinline__ void mma_bf16(float* c, const uint32_t* a, const uint32_t* b) {
    asm volatile(
        "mma.sync.aligned.m16n8k16.row.col.f32.bf16.bf16.f32 "
        "{%0,%1,%2,%3}, {%4,%5,%6,%7}, {%8,%9}, {%0,%1,%2,%3};"
        : "+f"(c[0]), "+f"(c[1]), "+f"(c[2]), "+f"(c[3])
        : "r"(a[0]), "r"(a[1]), "r"(a[2]), "r"(a[3]), "r"(b[0]), "r"(b[1]));
}

__device__ __forceinline__ void ld8(const float* __restrict__ p, float* d) {
    float4 v0 = *(const float4*)p;
    float4 v1 = *(const float4*)(p + 4);
    d[0] = v0.x; d[1] = v0.y; d[2] = v0.z; d[3] = v0.w;
    d[4] = v1.x; d[5] = v1.y; d[6] = v1.z; d[7] = v1.w;
}

// fp32[8] -> bf16 hi[8], lo[8]  (hi = rn(x), lo = rn(x - hi))
__device__ __forceinline__ void split8(const float* f, __nv_bfloat16* hi, __nv_bfloat16* lo) {
    uint32_t hw[4], lw[4];
#pragma unroll
    for (int i = 0; i < 4; i++) {
        __nv_bfloat16 h0 = __float2bfloat16_rn(f[2 * i]);
        __nv_bfloat16 h1 = __float2bfloat16_rn(f[2 * i + 1]);
        __nv_bfloat16 l0 = __float2bfloat16_rn(f[2 * i]     - __bfloat162float(h0));
        __nv_bfloat16 l1 = __float2bfloat16_rn(f[2 * i + 1] - __bfloat162float(h1));
        hw[i] = (uint32_t)__bfloat16_as_ushort(h0) | ((uint32_t)__bfloat16_as_ushort(h1) << 16);
        lw[i] = (uint32_t)__bfloat16_as_ushort(l0) | ((uint32_t)__bfloat16_as_ushort(l1) << 16);
    }
    *(uint4*)hi = make_uint4(hw[0], hw[1], hw[2], hw[3]);
    *(uint4*)lo = make_uint4(lw[0], lw[1], lw[2], lw[3]);
}

constexpr int PAD = 40;   // bf16 per smem row (80B stride: conflict-free ldmatrix)

// ---------------------------------------------------------------------------
// Mainloop: acc[4][4][4] += A[128,1024] * B[128,1024]^T (both K-major, ld=1024)
// via 3-term bf16-split mma.sync. CTA: 256 threads, warp grid 2(m) x 4(n),
// warp tile 64x32, K staged 32 per iteration, register prefetch.
// ---------------------------------------------------------------------------
__device__ __forceinline__ void mma_mainloop(const float* __restrict__ A,
                                             const float* __restrict__ B,
                                             float acc[4][4][4]) {
    __shared__ __align__(16) __nv_bfloat16 sAhi[128 * PAD];
    __shared__ __align__(16) __nv_bfloat16 sAlo[128 * PAD];
    __shared__ __align__(16) __nv_bfloat16 sBhi[128 * PAD];
    __shared__ __align__(16) __nv_bfloat16 sBlo[128 * PAD];

    const int tid = threadIdx.x;
    const int lane = tid & 31;
    const int wid = tid >> 5;
    const int wm = wid & 1;        // 0..1  (64-row slabs)
    const int wn = wid >> 1;       // 0..3  (32-col slabs)

#pragma unroll
    for (int i = 0; i < 4; i++)
#pragma unroll
        for (int j = 0; j < 4; j++)
#pragma unroll
            for (int k = 0; k < 4; k++) acc[i][j][k] = 0.f;

    // staging assignment: thread covers rows rA and rA+64, cols [kk, kk+8)
    const int rA = tid >> 2;
    const int kk = (tid & 3) * 8;

    float pA[16], pB[16];
    ld8(A + (size_t)rA * 1024 + kk, pA);
    ld8(A + (size_t)(rA + 64) * 1024 + kk, pA + 8);
    ld8(B + (size_t)rA * 1024 + kk, pB);
    ld8(B + (size_t)(rA + 64) * 1024 + kk, pB + 8);

    const uint32_t aHi = smem_u32(sAhi), aLo = smem_u32(sAlo);
    const uint32_t bHi = smem_u32(sBhi), bLo = smem_u32(sBlo);
    const int row16 = lane & 15;
    const int c8 = (lane >> 4) * 8;
    const uint32_t aOff = (uint32_t)((wm * 64 + row16) * (PAD * 2)) + (uint32_t)(c8 * 2);
    const uint32_t bOff = (uint32_t)((wn * 32 + row16) * (PAD * 2)) + (uint32_t)(c8 * 2);

    for (int ko = 0; ko < 32; ko++) {
        split8(pA,     &sAhi[rA * PAD + kk],        &sAlo[rA * PAD + kk]);
        split8(pA + 8, &sAhi[(rA + 64) * PAD + kk], &sAlo[(rA + 64) * PAD + kk]);
        split8(pB,     &sBhi[rA * PAD + kk],        &sBlo[rA * PAD + kk]);
        split8(pB + 8, &sBhi[(rA + 64) * PAD + kk], &sBlo[(rA + 64) * PAD + kk]);
        __syncthreads();

        if (ko < 31) {
            const float* An = A + (ko + 1) * 32;
            const float* Bn = B + (ko + 1) * 32;
            ld8(An + (size_t)rA * 1024 + kk, pA);
            ld8(An + (size_t)(rA + 64) * 1024 + kk, pA + 8);
            ld8(Bn + (size_t)rA * 1024 + kk, pB);
            ld8(Bn + (size_t)(rA + 64) * 1024 + kk, pB + 8);
        }

#pragma unroll
        for (int ks = 0; ks < 2; ks++) {
            const uint32_t koff = ks * 32;   // 16 bf16 = 32 bytes
            uint32_t ah[4][4], al[4][4], bhf[4][2], blf[4][2];

#pragma unroll
            for (int mf = 0; mf < 4; mf++)
                ldsm4(ah[mf][0], ah[mf][1], ah[mf][2], ah[mf][3],
                      aHi + aOff + mf * (16 * PAD * 2) + koff);
#pragma unroll
            for (int p = 0; p < 2; p++) {
                uint32_t r0, r1, r2, r3;
                ldsm4(r0, r1, r2, r3, bHi + bOff + p * (16 * PAD * 2) + koff);
                bhf[2 * p][0] = r0; bhf[2 * p][1] = r2;
                bhf[2 * p + 1][0] = r1; bhf[2 * p + 1][1] = r3;
            }
#pragma unroll
            for (int mf = 0; mf < 4; mf++)
#pragma unroll
                for (int nf = 0; nf < 4; nf++)
                    mma_bf16(acc[mf][nf], ah[mf], bhf[nf]);

#pragma unroll
            for (int p = 0; p < 2; p++) {
                uint32_t r0, r1, r2, r3;
                ldsm4(r0, r1, r2, r3, bLo + bOff + p * (16 * PAD * 2) + koff);
                blf[2 * p][0] = r0; blf[2 * p][1] = r2;
                blf[2 * p + 1][0] = r1; blf[2 * p + 1][1] = r3;
            }
#pragma unroll
            for (int mf = 0; mf < 4; mf++)
#pragma unroll
                for (int nf = 0; nf < 4; nf++)
                    mma_bf16(acc[mf][nf], ah[mf], blf[nf]);

#pragma unroll
            for (int mf = 0; mf < 4; mf++)
                ldsm4(al[mf][0], al[mf][1], al[mf][2], al[mf][3],
                      aLo + aOff + mf * (16 * PAD * 2) + koff);
#pragma unroll
            for (int mf = 0; mf < 4; mf++)
#pragma unroll
                for (int nf = 0; nf < 4; nf++)
                    mma_bf16(acc[mf][nf], al[mf], bhf[nf]);
        }
        __syncthreads();
    }
}

// ---------------------------------------------------------------------------
// GEMM1: xtran = x @ W^T + bias
// ---------------------------------------------------------------------------
__global__ __launch_bounds__(256)
void gemm1_kernel(const float* __restrict__ X, const float* __restrict__ W,
                  const float* __restrict__ bias) {
    const int m0 = blockIdx.y * 128;
    const int n0 = blockIdx.x * 128;

    float acc[4][4][4];
    mma_mainloop(X + (size_t)m0 * 1024, W + (size_t)n0 * 1024, acc);

    const int lane = threadIdx.x & 31, wid = threadIdx.x >> 5;
    const int wm = wid & 1, wn = wid >> 1;

#pragma unroll
    for (int mf = 0; mf < 4; mf++)
#pragma unroll
        for (int nf = 0; nf < 4; nf++) {
            int col = n0 + wn * 32 + nf * 8 + (lane & 3) * 2;
            float b0 = __ldg(&bias[col]), b1 = __ldg(&bias[col + 1]);
#pragma unroll
            for (int h = 0; h < 2; h++) {
                int row = m0 + wm * 64 + mf * 16 + (lane >> 2) + h * 8;
                float2 v = make_float2(acc[mf][nf][h * 2 + 0] + b0,
                                       acc[mf][nf][h * 2 + 1] + b1);
                *(float2*)&g_xtran[(size_t)row * 1024 + col] = v;
            }
        }
}

// ---------------------------------------------------------------------------
// GEMM2: weights[b] = xtran[b] @ x[b]^T with decay/opinion/exp(tanh)/mask epilogue
// ---------------------------------------------------------------------------
__global__ __launch_bounds__(256)
void gemm2_kernel(const float* __restrict__ X, const float* __restrict__ go,
                  const float* __restrict__ po, const float* __restrict__ gprob) {
    const int b  = blockIdx.z;
    const int m0 = blockIdx.y * 128;
    const int n0 = blockIdx.x * 128;

    float acc[4][4][4];
    mma_mainloop(g_xtran + (size_t)b * S * D + (size_t)m0 * 1024,
                 X       + (size_t)b * S * D + (size_t)n0 * 1024, acc);

    const int lane = threadIdx.x & 31, wid = threadIdx.x >> 5;
    const int wm = wid & 1, wn = wid >> 1;
    const float gp = __ldg(gprob);
    float* Cb = g_weights + (size_t)b * S * S;

#pragma unroll
    for (int mf = 0; mf < 4; mf++) {
#pragma unroll
        for (int h = 0; h < 2; h++) {
            int s = m0 + wm * 64 + mf * 16 + (lane >> 2) + h * 8;
            const float* goP = go + ((size_t)b * S + s) * 5;
            const float* poP = po + ((size_t)b * S + s) * 5;
            float ow = gp * (__ldg(&goP[1]) + __ldg(&goP[2])) +
                       (1.f - gp) * (__ldg(&poP[3]) + __ldg(&poP[4]));
#pragma unroll
            for (int nf = 0; nf < 4; nf++) {
                int t0 = n0 + wn * 32 + nf * 8 + (lane & 3) * 2;
                float2 v;
#pragma unroll
                for (int j = 0; j < 2; j++) {
                    int t = t0 + j;
                    float w = acc[mf][nf][h * 2 + j] * ow;
                    float loc = fabsf((float)(s - t));
                    w = __fdividef(w, loc + EPS);
                    float e2 = __expf(2.f * w);
                    float th = 1.f - __fdividef(2.f, e2 + 1.f);
                    float r = __expf(th);
                    if (s == t) r = 0.f;
                    ((float*)&v)[j] = r;
                }
                *(float2*)&Cb[(size_t)s * S + t0] = v;
            }
        }
    }
}

// ---------------------------------------------------------------------------
// GEMM3: out[b] = (weights[b] / rowsum) @ x[b]  (B = xT, K-major over t)
// ---------------------------------------------------------------------------
__global__ __launch_bounds__(256)
void gemm3_kernel(float* __restrict__ out) {
    const int b  = blockIdx.z;
    const int m0 = blockIdx.y * 128;
    const int n0 = blockIdx.x * 128;

    float acc[4][4][4];
    mma_mainloop(g_weights + (size_t)b * S * S + (size_t)m0 * 1024,
                 g_xT      + (size_t)b * S * D + (size_t)n0 * 1024, acc);

    const int lane = threadIdx.x & 31, wid = threadIdx.x >> 5;
    const int wm = wid & 1, wn = wid >> 1;
    float* Cb = out + (size_t)b * S * D;

#pragma unroll
    for (int mf = 0; mf < 4; mf++)
#pragma unroll
        for (int h = 0; h < 2; h++) {
            int s = m0 + wm * 64 + mf * 16 + (lane >> 2) + h * 8;
            float sc = 1.f / (g_rowsum[b * S + s] + EPS);
#pragma unroll
            for (int nf = 0; nf < 4; nf++) {
                int c0 = n0 + wn * 32 + nf * 8 + (lane & 3) * 2;
                float2 v = make_float2(acc[mf][nf][h * 2 + 0] * sc,
                                       acc[mf][nf][h * 2 + 1] * sc);
                *(float2*)&Cb[(size_t)s * 1024 + c0] = v;
            }
        }
}

// ---------------------------------------------------------------------------
// Transpose x per batch: g_xT[b][d][t] = x[b][t][d]
// ---------------------------------------------------------------------------
__global__ __launch_bounds__(256)
void transpose_kernel(const float* __restrict__ X) {
    __shared__ float tile[32][33];
    int b = blockIdx.z;
    int t0 = blockIdx.x * 32;
    int d0 = blockIdx.y * 32;
    const float* src = X + (size_t)b * S * D;
    float* dst = g_xT + (size_t)b * S * D;
    int tx = threadIdx.x & 31, ty = threadIdx.x >> 5;
#pragma unroll
    for (int i = 0; i < 32; i += 8)
        tile[ty + i][tx] = src[(size_t)(t0 + ty + i) * D + d0 + tx];
    __syncthreads();
#pragma unroll
    for (int i = 0; i < 32; i += 8)
        dst[(size_t)(d0 + ty + i) * S + t0 + tx] = tile[tx][ty + i];
}

// ---------------------------------------------------------------------------
// Rowsum over weights rows
// ---------------------------------------------------------------------------
__global__ __launch_bounds__(256)
void rowsum_kernel() {
    const int row = blockIdx.x;
    const float* p = g_weights + (size_t)row * S;
    const int tid = threadIdx.x;

    float4 v = *(const float4*)&p[tid * 4];
    float s = v.x + v.y + v.z + v.w;
#pragma unroll
    for (int off = 16; off > 0; off >>= 1)
        s += __shfl_down_sync(0xFFFFFFFFu, s, off);

    __shared__ float warpsum[8];
    if ((tid & 31) == 0) warpsum[tid >> 5] = s;
    __syncthreads();
    if (tid < 8) {
        float t = warpsum[tid];
#pragma unroll
        for (int off = 4; off > 0; off >>= 1)
            t += __shfl_down_sync(0xFFu, t, off);
        if (tid == 0) g_rowsum[row] = t;
    }
}

// ---------------------------------------------------------------------------
extern "C" void kernel_launch(void* const* d_in, const int* in_sizes, int n_in,
                              void* d_out, int out_size)
{
    const float* x     = (const float*)d_in[0];  // [32,1024,1024]
    const float* W     = (const float*)d_in[1];  // [1024,1024]
    const float* bias  = (const float*)d_in[2];  // [1024]
    const float* go    = (const float*)d_in[3];  // [32,1024,5]
    const float* po    = (const float*)d_in[4];  // [32,1024,5]
    const float* gprob = (const float*)d_in[5];  // scalar
    float* out = (float*)d_out;

    transpose_kernel<<<dim3(32, 32, BATCH), 256>>>(x);
    gemm1_kernel<<<dim3(8, 256), 256>>>(x, W, bias);
    gemm2_kernel<<<dim3(8, 8, BATCH), 256>>>(x, go, po, gprob);
    rowsum_kernel<<<dim3(BATCH * S), 256>>>();
    gemm3_kernel<<<dim3(8, 8, BATCH), 256>>>(out);
}